// round 8
// baseline (speedup 1.0000x reference)
#include <cuda_runtime.h>
#include <cuda_fp16.h>
#include <math.h>

// Persistent-kernel LSTM decoder. B=64, H=1024, L=2, T=128.
// 128 CTAs (1/SM), 512 threads (16 warps) per CTA.
// Warp = (khalf, colgrp, wm): each warp does the (16-row M-tile x 16-col
// gate tile) over HALF of each chunk's k16s -> 2x warps vs R4 with identical
// total LDSM/HMMA work => occupancy 12.5%->25% to hide the L1/LDSM latency
// that the R7 profile showed (L1=40%, tensor=18.5%, issue=19.6%).
// Cross-khalf gate reduction + 4-way FC reduction in SMEM at the epilogue.

#define BATCH   64
#define HID     1024
#define TSTEPS  128
#define NCTA    128
#define THREADS 512
#define SA      136    // streamed act chunk row stride (halfs)
#define SW      136    // streamed weight chunk row stride (halfs)
#define SR      1032   // resident weight row stride (halfs)
#define KC      128    // K chunk

// ---------------- device globals (pre-permuted fp16 weights + state) -------
__device__ __half g_Wih_p[2 * NCTA * 32 * HID];   // [l][cta][pn][k]
__device__ __half g_Whh_p[2 * NCTA * 32 * HID];
__device__ __half g_Wfc_p[NCTA * 8 * HID];        // [cta][u][k]
__device__ __half g_hbuf[4 * BATCH * HID];        // [l*2+parity][b][h]
__device__ __half g_x0[BATCH * HID];
__device__ unsigned g_bar;

// ---------------- small asm helpers ---------------------------------------
__device__ __forceinline__ unsigned sptr(const void* p) {
    return (unsigned)__cvta_generic_to_shared(p);
}
__device__ __forceinline__ void cp16(void* s, const void* g) {      // weights (.ca)
    asm volatile("cp.async.ca.shared.global [%0], [%1], 16;" :: "r"(sptr(s)), "l"(g));
}
__device__ __forceinline__ void cp16cg(void* s, const void* g) {    // acts (.cg)
    asm volatile("cp.async.cg.shared.global [%0], [%1], 16;" :: "r"(sptr(s)), "l"(g));
}
__device__ __forceinline__ void cp_commit() {
    asm volatile("cp.async.commit_group;");
}
template<int N> __device__ __forceinline__ void cp_wait() {
    asm volatile("cp.async.wait_group %0;" :: "n"(N));
}
__device__ __forceinline__ void ldsm_x4(unsigned &r0, unsigned &r1, unsigned &r2, unsigned &r3, unsigned a) {
    asm volatile("ldmatrix.sync.aligned.m8n8.x4.shared.b16 {%0,%1,%2,%3}, [%4];"
                 : "=r"(r0), "=r"(r1), "=r"(r2), "=r"(r3) : "r"(a));
}
__device__ __forceinline__ void ldsm_x2(unsigned &r0, unsigned &r1, unsigned a) {
    asm volatile("ldmatrix.sync.aligned.m8n8.x2.shared.b16 {%0,%1}, [%2];"
                 : "=r"(r0), "=r"(r1) : "r"(a));
}
__device__ __forceinline__ void hmma(float d[4], unsigned a0, unsigned a1, unsigned a2, unsigned a3,
                                     unsigned b0, unsigned b1) {
    asm volatile("mma.sync.aligned.m16n8k16.row.col.f32.f16.f16.f32 "
                 "{%0,%1,%2,%3},{%4,%5,%6,%7},{%8,%9},{%0,%1,%2,%3};"
                 : "+f"(d[0]), "+f"(d[1]), "+f"(d[2]), "+f"(d[3])
                 : "r"(a0), "r"(a1), "r"(a2), "r"(a3), "r"(b0), "r"(b1));
}
__device__ __forceinline__ float sig_(float x) { return 1.0f / (1.0f + __expf(-x)); }

// ---------------- single merged prep kernel ---------------------------------
// permuted col index pn -> (gate, unit):
//   nn=pn&15; half=nn>>3; a=(nn&7)>>1; s=nn&1; gate=half*2+s; unit=(pn>>4)*4+a
__global__ void prep_all(const float* __restrict__ Wih, const float* __restrict__ Whh,
                         const float* __restrict__ h0,  const float* __restrict__ Wfc) {
    int i = blockIdx.x * blockDim.x + threadIdx.x;
    int stride = gridDim.x * blockDim.x;
    const int totalG = 2 * NCTA * 32 * HID;
    for (int e = i; e < totalG; e += stride) {
        int k = e & (HID - 1);
        int pn = (e >> 10) & 31;
        int cta = (e >> 15) & (NCTA - 1);
        int l = e >> 22;
        int nn = pn & 15, half = nn >> 3, a = (nn & 7) >> 1, s = nn & 1;
        int gate = half * 2 + s, unit = (pn >> 4) * 4 + a;
        size_t src = (size_t)l * 4 * HID * HID + (size_t)(gate * HID + cta * 8 + unit) * HID + k;
        g_Wih_p[e] = __float2half_rn(Wih[src]);
        g_Whh_p[e] = __float2half_rn(Whh[src]);
    }
    for (int e = i; e < NCTA * 8 * HID; e += stride) {
        int k = e & (HID - 1);
        int u = (e >> 10) & 7;
        int cta = e >> 13;
        g_Wfc_p[e] = __float2half_rn(Wfc[(size_t)(cta * 8 + u) * HID + k]);
    }
    for (int e = i; e < BATCH * HID; e += stride) g_x0[e] = __float2half_rn(h0[e]);
    for (int e = i; e < 4 * BATCH * HID; e += stride) g_hbuf[e] = __float2half_rn(0.0f);
    if (i == 0) g_bar = 0;
}

// ---------------- split grid barrier ---------------------------------------
__device__ __forceinline__ void gbar_arrive() {
    __threadfence();
    __syncthreads();
    if (threadIdx.x == 0) atomicAdd(&g_bar, 1u);
}
__device__ __forceinline__ void gbar_wait(unsigned target) {
    if (threadIdx.x == 0) {
        unsigned v;
        do {
            asm volatile("ld.acquire.gpu.u32 %0, [%1];" : "=r"(v) : "l"(&g_bar));
        } while (v < target);
    }
    __syncthreads();
}

// ---------------- staging (512 threads) -------------------------------------
__device__ __forceinline__ void stage_act(__half* dst, const __half* src, int k0, int tid) {
    #pragma unroll
    for (int i = 0; i < 2; i++) {
        int e = tid + i * THREADS;          // 1024 ops: 64 rows x 16 segs
        int r = e >> 4, sg = e & 15;
        cp16cg(dst + r * SA + sg * 8, src + r * HID + k0 + sg * 8);
    }
}
__device__ __forceinline__ void stage_w(__half* dst, const __half* src, int k0, int tid) {
    int r = tid >> 4, sg = tid & 15;        // 512 ops: 32 rows x 16 segs
    cp16(dst + r * SW + sg * 8, src + r * HID + k0 + sg * 8);
}

// ---------------- main persistent kernel ------------------------------------
__global__ __launch_bounds__(THREADS, 1) void lstm_persist(
    const float* __restrict__ bih, const float* __restrict__ bhh,
    const float* __restrict__ bfc, float* __restrict__ out)
{
    extern __shared__ __align__(16) unsigned char smem_raw[];
    __half* whhS  = (__half*)smem_raw;            // [2][32][SR]
    __half* wfcS  = whhS + 2 * 32 * SR;           // [8][SR]
    __half* xbufS = wfcS + 8 * SR;                // [2][64][SA]
    __half* wbufS = xbufS + 2 * 64 * SA;          // [2][32][SW]
    float*  cS    = (float*)(wbufS + 2 * 32 * SW);// [2][64][8]
    float*  biasS = cS + 2 * 64 * 8;              // [2][32]
    float*  fcbS  = biasS + 64;                   // [8]
    float*  redS  = fcbS + 8;                     // [8 warps][32][8] gate khalf-reduce
    float*  fcrS  = redS + 8 * 32 * 8;            // [16 warps][32][4] FC reduce

    const int tid  = threadIdx.x;
    const int warp = tid >> 5;
    const int lane = tid & 31;
    const int wm     = warp & 3;          // M-tile (16 rows)
    const int colgrp = (warp >> 2) & 1;   // 16-col gate group
    const int khalf  = warp >> 3;         // k16 half within chunk
    const int cta  = blockIdx.x;
    const int j0   = cta * 8;

    // ---- load resident weights (Whh both layers + Wfc slice) ----
    for (int l = 0; l < 2; l++) {
        const __half* src = g_Whh_p + (size_t)(l * NCTA + cta) * 32 * HID;
        for (int i = 0; i < 8; i++) {
            int e = tid + i * THREADS;      // 32 rows x 128 segs
            int r = e >> 7, sg = e & 127;
            cp16(whhS + l * 32 * SR + r * SR + sg * 8, src + r * HID + sg * 8);
        }
    }
    {
        const __half* src = g_Wfc_p + (size_t)cta * 8 * HID;
        for (int i = 0; i < 2; i++) {
            int e = tid + i * THREADS;      // 8 rows x 128 segs
            int r = e >> 7, sg = e & 127;
            cp16(wfcS + r * SR + sg * 8, src + r * HID + sg * 8);
        }
    }
    cp_commit();
    // ---- biases / cell state ----
    if (tid < 64) {
        int l = tid >> 5, pn = tid & 31;
        int nn = pn & 15, half = nn >> 3, a = (nn & 7) >> 1, s = nn & 1;
        int gate = half * 2 + s, unit = (pn >> 4) * 4 + a;
        int row = gate * HID + j0 + unit;
        biasS[l * 32 + pn] = bih[l * 4 * HID + row] + bhh[l * 4 * HID + row];
    }
    if (tid < 8) fcbS[tid] = bfc[j0 + tid];
    #pragma unroll
    for (int i = 0; i < 2; i++) cS[tid + i * THREADS] = 0.0f;
    cp_wait<0>();
    __syncthreads();

    // precomputed shared addresses (bytes)
    const unsigned xb0 = sptr(xbufS) + ((wm * 16 + (lane & 15)) * SA + (lane >> 4) * 8) * 2;
    const unsigned xb1 = xb0 + 64 * SA * 2;
    const unsigned wb0 = sptr(wbufS) + ((colgrp * 16 + (lane & 15)) * SW + (lane >> 4) * 8) * 2;
    const unsigned wb1 = wb0 + 32 * SW * 2;
    const unsigned whA[2] = {
        sptr(whhS) + ((colgrp * 16 + (lane & 15)) * SR + (lane >> 4) * 8) * 2,
        sptr(whhS) + ((32 + colgrp * 16 + (lane & 15)) * SR + (lane >> 4) * 8) * 2 };
    const unsigned fcA = sptr(wfcS) + (((lane & 7)) * SR + ((lane >> 3) & 1) * 8) * 2;

    unsigned barTarget = 0;
    const int r = lane >> 2, a4 = lane & 3;
    const int uloc = colgrp * 4 + a4;
    const int k16base = khalf * 4;        // this warp's first k16 in each chunk

    for (int t = 0; t < TSTEPS; t++) {
        const int p = t & 1, q = p ^ 1;
        #pragma unroll 1
        for (int l = 0; l < 2; l++) {
            const __half* xsrc = (l == 0)
                ? ((t == 0) ? g_x0 : g_hbuf + (2 + q) * BATCH * HID)
                : g_hbuf + (0 + p) * BATCH * HID;
            const __half* hsrc = g_hbuf + (l * 2 + q) * BATCH * HID;
            __half* hdst = g_hbuf + (l * 2 + p) * BATCH * HID;
            const __half* wsrc = g_Wih_p + (size_t)(l * NCTA + cta) * 32 * HID;
            const bool fc_phase = (l == 0) && (t > 0);

            float acc0[2][4] = {{0,0,0,0},{0,0,0,0}};
            float acc1[2][4] = {{0,0,0,0},{0,0,0,0}};
            float fca[4] = {0, 0, 0, 0};

            // ===== part A: h_rec @ Whh (resident; no fresh barrier needed) ==
            stage_act(xbufS, hsrc, 0, tid);
            stage_w(wbufS, wsrc, 0, tid);
            cp_commit();
            #pragma unroll 1
            for (int kc = 0; kc < HID / KC; kc++) {
                if (kc + 1 < HID / KC) {
                    stage_act(xbufS + ((kc + 1) & 1) * 64 * SA, hsrc, (kc + 1) * KC, tid);
                    cp_commit();
                    cp_wait<1>();
                } else cp_wait<0>();
                __syncthreads();
                const unsigned xb = (kc & 1) ? xb1 : xb0;
                #pragma unroll
                for (int j = 0; j < 4; j++) {
                    const int k16 = k16base + j;
                    const int e = j & 1;
                    unsigned a0, a1, a2, a3, b0, b1, b2, b3;
                    ldsm_x4(a0, a1, a2, a3, xb + k16 * 32);
                    ldsm_x4(b0, b1, b2, b3, whA[l] + (kc * KC + k16 * 16) * 2);
                    hmma(acc0[e], a0, a1, a2, a3, b0, b2);
                    hmma(acc1[e], a0, a1, a2, a3, b1, b3);
                }
                __syncthreads();
            }

            // ===== barrier wait (mostly satisfied already) =====
            gbar_wait(barTarget);

            // ===== part B: x @ Wih (streamed) + FC (split over all warps) ===
            stage_act(xbufS, xsrc, 0, tid);
            cp_commit();
            #pragma unroll 1
            for (int kc = 0; kc < HID / KC; kc++) {
                if (kc + 1 < HID / KC) {
                    stage_act(xbufS + ((kc + 1) & 1) * 64 * SA, xsrc, (kc + 1) * KC, tid);
                    stage_w(wbufS + ((kc + 1) & 1) * 32 * SW, wsrc, (kc + 1) * KC, tid);
                    cp_commit();
                    cp_wait<1>();
                } else cp_wait<0>();
                __syncthreads();
                const unsigned xb = (kc & 1) ? xb1 : xb0;
                const unsigned wb = (kc & 1) ? wb1 : wb0;
                #pragma unroll
                for (int j = 0; j < 4; j++) {
                    const int k16 = k16base + j;
                    const int e = j & 1;
                    unsigned a0, a1, a2, a3, b0, b1, b2, b3;
                    ldsm_x4(a0, a1, a2, a3, xb + k16 * 32);
                    ldsm_x4(b0, b1, b2, b3, wb + k16 * 32);
                    hmma(acc0[e], a0, a1, a2, a3, b0, b2);
                    hmma(acc1[e], a0, a1, a2, a3, b1, b3);
                    if (fc_phase && e == colgrp) {
                        unsigned f0, f1;
                        ldsm_x2(f0, f1, fcA + (kc * KC + k16 * 16) * 2);
                        hmma(fca, a0, a1, a2, a3, f0, f1);
                    }
                }
                __syncthreads();
            }

            // ===== epilogue: khalf-reduce gates, 4-way reduce FC ============
            float s0[4], s1[4];
            #pragma unroll
            for (int i = 0; i < 4; i++) {
                s0[i] = acc0[0][i] + acc0[1][i];
                s1[i] = acc1[0][i] + acc1[1][i];
            }
            if (khalf == 1) {
                float* rp_ = redS + ((colgrp * 4 + wm) * 32 + lane) * 8;
                #pragma unroll
                for (int i = 0; i < 4; i++) { rp_[i] = s0[i]; rp_[4 + i] = s1[i]; }
            }
            if (fc_phase) {
                float* fp_ = fcrS + (warp * 32 + lane) * 4;
                #pragma unroll
                for (int i = 0; i < 4; i++) fp_[i] = fca[i];
            }
            __syncthreads();
            if (khalf == 0) {
                const float* rp_ = redS + ((colgrp * 4 + wm) * 32 + lane) * 8;
                #pragma unroll
                for (int i = 0; i < 4; i++) { s0[i] += rp_[i]; s1[i] += rp_[4 + i]; }

                float* crow = cS + l * 64 * 8;
                #pragma unroll
                for (int rp = 0; rp < 2; rp++) {
                    int b = wm * 16 + r + rp * 8;
                    int k = rp * 2;
                    float iv = s0[k+0] + biasS[l * 32 + colgrp * 16 + a4 * 2 + 0];
                    float fv = s0[k+1] + biasS[l * 32 + colgrp * 16 + a4 * 2 + 1];
                    float gv = s1[k+0] + biasS[l * 32 + colgrp * 16 + 8 + a4 * 2 + 0];
                    float ov = s1[k+1] + biasS[l * 32 + colgrp * 16 + 8 + a4 * 2 + 1];
                    float cn = sig_(fv) * crow[b * 8 + uloc] + sig_(iv) * tanhf(gv);
                    crow[b * 8 + uloc] = cn;
                    hdst[b * HID + j0 + uloc] = __float2half_rn(sig_(ov) * tanhf(cn));
                }
                if (fc_phase && colgrp == 0) {
                    float* op = out + (size_t)(t - 1) * BATCH * HID;
                    #pragma unroll
                    for (int rp = 0; rp < 2; rp++) {
                        int b = wm * 16 + r + rp * 8;
                        int k = rp * 2;
                        #pragma unroll
                        for (int cc = 0; cc < 2; cc++) {
                            float v = fcbS[a4 * 2 + cc];
                            #pragma unroll
                            for (int w4 = 0; w4 < 4; w4++)
                                v += fcrS[((w4 * 4 + wm) * 32 + lane) * 4 + k + cc];
                            op[b * HID + j0 + a4 * 2 + cc] = v;
                        }
                    }
                }
            }
            gbar_arrive();
            barTarget += NCTA;
        }
    }

    // ===== final FC for t = T-1 (x = h1 written at t=127, parity 1) =====
    {
        gbar_wait(barTarget);
        const __half* xsrc = g_hbuf + (2 + 1) * BATCH * HID;
        float fca[4] = {0, 0, 0, 0};
        stage_act(xbufS, xsrc, 0, tid);
        cp_commit();
        #pragma unroll 1
        for (int kc = 0; kc < HID / KC; kc++) {
            if (kc + 1 < HID / KC) {
                stage_act(xbufS + ((kc + 1) & 1) * 64 * SA, xsrc, (kc + 1) * KC, tid);
                cp_commit();
                cp_wait<1>();
            } else cp_wait<0>();
            __syncthreads();
            const unsigned xb = (kc & 1) ? xb1 : xb0;
            #pragma unroll
            for (int j = 0; j < 4; j++) {
                const int k16 = k16base + j;
                if ((j & 1) == colgrp) {
                    unsigned a0, a1, a2, a3, f0, f1;
                    ldsm_x4(a0, a1, a2, a3, xb + k16 * 32);
                    ldsm_x2(f0, f1, fcA + (kc * KC + k16 * 16) * 2);
                    hmma(fca, a0, a1, a2, a3, f0, f1);
                }
            }
            __syncthreads();
        }
        {
            float* fp_ = fcrS + (warp * 32 + lane) * 4;
            #pragma unroll
            for (int i = 0; i < 4; i++) fp_[i] = fca[i];
        }
        __syncthreads();
        if (khalf == 0 && colgrp == 0) {
            float* op = out + (size_t)(TSTEPS - 1) * BATCH * HID;
            #pragma unroll
            for (int rp = 0; rp < 2; rp++) {
                int b = wm * 16 + r + rp * 8;
                int k = rp * 2;
                #pragma unroll
                for (int cc = 0; cc < 2; cc++) {
                    float v = fcbS[a4 * 2 + cc];
                    #pragma unroll
                    for (int w4 = 0; w4 < 4; w4++)
                        v += fcrS[((w4 * 4 + wm) * 32 + lane) * 4 + k + cc];
                    op[b * HID + j0 + a4 * 2 + cc] = v;
                }
            }
        }
    }
}

// ---------------- host launch -----------------------------------------------
extern "C" void kernel_launch(void* const* d_in, const int* in_sizes, int n_in,
                              void* d_out, int out_size) {
    const float* h0  = (const float*)d_in[0];
    const float* Wih = (const float*)d_in[1];
    const float* Whh = (const float*)d_in[2];
    const float* bih = (const float*)d_in[3];
    const float* bhh = (const float*)d_in[4];
    const float* Wfc = (const float*)d_in[5];
    const float* bfc = (const float*)d_in[6];
    float* out = (float*)d_out;

    const int smem = (2 * 32 * SR + 8 * SR + 2 * 64 * SA + 2 * 32 * SW) * 2
                   + (2 * 64 * 8 + 64 + 8 + 8 * 32 * 8 + 16 * 32 * 4) * 4;
    cudaFuncSetAttribute(lstm_persist, cudaFuncAttributeMaxDynamicSharedMemorySize, smem);

    prep_all<<<2048, 256>>>(Wih, Whh, h0, Wfc);
    lstm_persist<<<NCTA, THREADS, smem>>>(bih, bhh, bfc, out);
}

// round 9
// speedup vs baseline: 1.5166x; 1.5166x over previous
#include <cuda_runtime.h>
#include <cuda_fp16.h>
#include <math.h>

// Persistent-kernel LSTM decoder. B=64, H=1024, L=2, T=128.
// 128 CTAs (1/SM), 256 threads (8 warps).
// R9: warp = (ks, m2) computes a 32-row x 32-col tile over k16s {ks, ks+4}
// of each 128-K chunk -> halves LDSM/L1 traffic vs R4 (A dup x2->x1 wider,
// B dup x4->x2) and gives 8 independent HMMA accumulator chains.
// Epilogue: 4-way k-split reduction through stale xbufS scratch.
// Everything else (staging, split grid barrier, phase order) = R4.

#define BATCH   64
#define HID     1024
#define TSTEPS  128
#define NCTA    128
#define THREADS 256
#define SA      136    // streamed act chunk row stride (halfs)
#define SW      136    // streamed weight chunk row stride (halfs)
#define SR      1032   // resident weight row stride (halfs)
#define KC      128    // K chunk

// ---------------- device globals (pre-permuted fp16 weights + state) -------
__device__ __half g_Wih_p[2 * NCTA * 32 * HID];   // [l][cta][pn][k]
__device__ __half g_Whh_p[2 * NCTA * 32 * HID];
__device__ __half g_Wfc_p[NCTA * 8 * HID];        // [cta][u][k]
__device__ __half g_hbuf[4 * BATCH * HID];        // [l*2+parity][b][h]
__device__ __half g_x0[BATCH * HID];
__device__ unsigned g_bar;

// ---------------- small asm helpers ---------------------------------------
__device__ __forceinline__ unsigned sptr(const void* p) {
    return (unsigned)__cvta_generic_to_shared(p);
}
__device__ __forceinline__ void cp16(void* s, const void* g) {      // weights (.ca)
    asm volatile("cp.async.ca.shared.global [%0], [%1], 16;" :: "r"(sptr(s)), "l"(g));
}
__device__ __forceinline__ void cp16cg(void* s, const void* g) {    // acts (.cg)
    asm volatile("cp.async.cg.shared.global [%0], [%1], 16;" :: "r"(sptr(s)), "l"(g));
}
__device__ __forceinline__ void cp_commit() {
    asm volatile("cp.async.commit_group;");
}
template<int N> __device__ __forceinline__ void cp_wait() {
    asm volatile("cp.async.wait_group %0;" :: "n"(N));
}
__device__ __forceinline__ void ldsm_x4(unsigned &r0, unsigned &r1, unsigned &r2, unsigned &r3, unsigned a) {
    asm volatile("ldmatrix.sync.aligned.m8n8.x4.shared.b16 {%0,%1,%2,%3}, [%4];"
                 : "=r"(r0), "=r"(r1), "=r"(r2), "=r"(r3) : "r"(a));
}
__device__ __forceinline__ void ldsm_x2(unsigned &r0, unsigned &r1, unsigned a) {
    asm volatile("ldmatrix.sync.aligned.m8n8.x2.shared.b16 {%0,%1}, [%2];"
                 : "=r"(r0), "=r"(r1) : "r"(a));
}
__device__ __forceinline__ void hmma(float d[4], unsigned a0, unsigned a1, unsigned a2, unsigned a3,
                                     unsigned b0, unsigned b1) {
    asm volatile("mma.sync.aligned.m16n8k16.row.col.f32.f16.f16.f32 "
                 "{%0,%1,%2,%3},{%4,%5,%6,%7},{%8,%9},{%0,%1,%2,%3};"
                 : "+f"(d[0]), "+f"(d[1]), "+f"(d[2]), "+f"(d[3])
                 : "r"(a0), "r"(a1), "r"(a2), "r"(a3), "r"(b0), "r"(b1));
}
__device__ __forceinline__ float sig_(float x) { return 1.0f / (1.0f + __expf(-x)); }

// ---------------- single merged prep kernel ---------------------------------
// permuted col index pn -> (gate, unit):
//   nn=pn&15; half=nn>>3; a=(nn&7)>>1; s=nn&1; gate=half*2+s; unit=(pn>>4)*4+a
__global__ void prep_all(const float* __restrict__ Wih, const float* __restrict__ Whh,
                         const float* __restrict__ h0,  const float* __restrict__ Wfc) {
    int i = blockIdx.x * blockDim.x + threadIdx.x;
    int stride = gridDim.x * blockDim.x;
    const int totalG = 2 * NCTA * 32 * HID;
    for (int e = i; e < totalG; e += stride) {
        int k = e & (HID - 1);
        int pn = (e >> 10) & 31;
        int cta = (e >> 15) & (NCTA - 1);
        int l = e >> 22;
        int nn = pn & 15, half = nn >> 3, a = (nn & 7) >> 1, s = nn & 1;
        int gate = half * 2 + s, unit = (pn >> 4) * 4 + a;
        size_t src = (size_t)l * 4 * HID * HID + (size_t)(gate * HID + cta * 8 + unit) * HID + k;
        g_Wih_p[e] = __float2half_rn(Wih[src]);
        g_Whh_p[e] = __float2half_rn(Whh[src]);
    }
    for (int e = i; e < NCTA * 8 * HID; e += stride) {
        int k = e & (HID - 1);
        int u = (e >> 10) & 7;
        int cta = e >> 13;
        g_Wfc_p[e] = __float2half_rn(Wfc[(size_t)(cta * 8 + u) * HID + k]);
    }
    for (int e = i; e < BATCH * HID; e += stride) g_x0[e] = __float2half_rn(h0[e]);
    for (int e = i; e < 4 * BATCH * HID; e += stride) g_hbuf[e] = __float2half_rn(0.0f);
    if (i == 0) g_bar = 0;
}

// ---------------- split grid barrier ---------------------------------------
__device__ __forceinline__ void gbar_arrive() {
    __threadfence();
    __syncthreads();
    if (threadIdx.x == 0) atomicAdd(&g_bar, 1u);
}
__device__ __forceinline__ void gbar_wait(unsigned target) {
    if (threadIdx.x == 0) {
        unsigned v;
        do {
            asm volatile("ld.acquire.gpu.u32 %0, [%1];" : "=r"(v) : "l"(&g_bar));
        } while (v < target);
    }
    __syncthreads();
}

// ---------------- staging ---------------------------------------------------
__device__ __forceinline__ void stage_act(__half* dst, const __half* src, int k0, int tid) {
    #pragma unroll
    for (int i = 0; i < 4; i++) {
        int e = tid + i * THREADS;          // 1024 ops: 64 rows x 16 segs
        int r = e >> 4, sg = e & 15;
        cp16cg(dst + r * SA + sg * 8, src + r * HID + k0 + sg * 8);
    }
}
__device__ __forceinline__ void stage_w(__half* dst, const __half* src, int k0, int tid) {
    #pragma unroll
    for (int i = 0; i < 2; i++) {
        int e = tid + i * THREADS;          // 512 ops: 32 rows x 16 segs
        int r = e >> 4, sg = e & 15;
        cp16(dst + r * SW + sg * 8, src + r * HID + k0 + sg * 8);
    }
}

// ---------------- main persistent kernel ------------------------------------
__global__ __launch_bounds__(THREADS, 1) void lstm_persist(
    const float* __restrict__ bih, const float* __restrict__ bhh,
    const float* __restrict__ bfc, float* __restrict__ out)
{
    extern __shared__ __align__(16) unsigned char smem_raw[];
    __half* whhS  = (__half*)smem_raw;            // [2][32][SR]
    __half* wfcS  = whhS + 2 * 32 * SR;           // [8][SR]
    __half* xbufS = wfcS + 8 * SR;                // [2][64][SA] (also epilogue scratch)
    __half* wbufS = xbufS + 2 * 64 * SA;          // [2][32][SW]
    float*  cS    = (float*)(wbufS + 2 * 32 * SW);// [2][64][8]
    float*  biasS = cS + 2 * 64 * 8;              // [2][32]
    float*  fcbS  = biasS + 64;                   // [8]
    float*  xscr  = (float*)xbufS;                // epilogue reduce scratch (stale ring)

    const int tid  = threadIdx.x;
    const int warp = tid >> 5;
    const int lane = tid & 31;
    const int m2   = warp & 1;     // 32-row M half
    const int ks   = warp >> 1;    // k16 split (k16 in {ks, ks+4})
    const int cta  = blockIdx.x;
    const int j0   = cta * 8;

    // ---- load resident weights (Whh both layers + Wfc slice) ----
    for (int l = 0; l < 2; l++) {
        const __half* src = g_Whh_p + (size_t)(l * NCTA + cta) * 32 * HID;
        for (int i = 0; i < 16; i++) {
            int e = tid + i * THREADS;      // 32 rows x 128 segs
            int r = e >> 7, sg = e & 127;
            cp16(whhS + l * 32 * SR + r * SR + sg * 8, src + r * HID + sg * 8);
        }
    }
    {
        const __half* src = g_Wfc_p + (size_t)cta * 8 * HID;
        for (int i = 0; i < 4; i++) {
            int e = tid + i * THREADS;      // 8 rows x 128 segs
            int r = e >> 7, sg = e & 127;
            cp16(wfcS + r * SR + sg * 8, src + r * HID + sg * 8);
        }
    }
    cp_commit();
    // ---- biases / cell state ----
    if (tid < 64) {
        int l = tid >> 5, pn = tid & 31;
        int nn = pn & 15, half = nn >> 3, a = (nn & 7) >> 1, s = nn & 1;
        int gate = half * 2 + s, unit = (pn >> 4) * 4 + a;
        int row = gate * HID + j0 + unit;
        biasS[l * 32 + pn] = bih[l * 4 * HID + row] + bhh[l * 4 * HID + row];
    }
    if (tid < 8) fcbS[tid] = bfc[j0 + tid];
    #pragma unroll
    for (int i = 0; i < 4; i++) cS[tid + i * THREADS] = 0.0f;
    cp_wait<0>();
    __syncthreads();

    // per-lane fragment addresses (bytes)
    //   A: two 16-row frags (mf) of this warp's 32-row tile
    const unsigned xbA0[2] = {
        sptr(xbufS) + ((m2 * 32 + 0  + (lane & 15)) * SA + (lane >> 4) * 8) * 2,
        sptr(xbufS) + ((m2 * 32 + 16 + (lane & 15)) * SA + (lane >> 4) * 8) * 2 };
    const unsigned XB1 = 64 * SA * 2;            // act ring buffer-1 delta
    //   B streamed (Wih): two 16-col groups
    const unsigned wbB0[2] = {
        sptr(wbufS) + ((0  + (lane & 15)) * SW + (lane >> 4) * 8) * 2,
        sptr(wbufS) + ((16 + (lane & 15)) * SW + (lane >> 4) * 8) * 2 };
    const unsigned WB1 = 32 * SW * 2;            // Wih ring buffer-1 delta
    //   B resident (Whh): [l][cg]
    const unsigned whB[2][2] = {
        { sptr(whhS) + ((0  + (lane & 15)) * SR + (lane >> 4) * 8) * 2,
          sptr(whhS) + ((16 + (lane & 15)) * SR + (lane >> 4) * 8) * 2 },
        { sptr(whhS) + ((32 + 0  + (lane & 15)) * SR + (lane >> 4) * 8) * 2,
          sptr(whhS) + ((32 + 16 + (lane & 15)) * SR + (lane >> 4) * 8) * 2 } };
    const unsigned fcA = sptr(wfcS) + (((lane & 7)) * SR + ((lane >> 3) & 1) * 8) * 2;

    unsigned barTarget = 0;
    const int r = lane >> 2, a4 = lane & 3;

    for (int t = 0; t < TSTEPS; t++) {
        const int p = t & 1, q = p ^ 1;
        #pragma unroll 1
        for (int l = 0; l < 2; l++) {
            const __half* xsrc = (l == 0)
                ? ((t == 0) ? g_x0 : g_hbuf + (2 + q) * BATCH * HID)
                : g_hbuf + (0 + p) * BATCH * HID;
            const __half* hsrc = g_hbuf + (l * 2 + q) * BATCH * HID;
            __half* hdst = g_hbuf + (l * 2 + p) * BATCH * HID;
            const __half* wsrc = g_Wih_p + (size_t)(l * NCTA + cta) * 32 * HID;
            const bool fc_phase = (l == 0) && (t > 0);

            float acc[2][4][4];                 // [mf][nf][frag]
            #pragma unroll
            for (int a = 0; a < 2; a++)
                #pragma unroll
                for (int b = 0; b < 4; b++)
                    #pragma unroll
                    for (int c2 = 0; c2 < 4; c2++) acc[a][b][c2] = 0.0f;
            float fca[2][4] = {{0,0,0,0},{0,0,0,0}};

            // ===== part A: h_rec @ Whh (resident; no fresh barrier needed;
            //       hsrc written two phases ago). Prefetch Wih chunk 0. =====
            stage_act(xbufS, hsrc, 0, tid);
            stage_w(wbufS, wsrc, 0, tid);
            cp_commit();
            #pragma unroll 1
            for (int kc = 0; kc < HID / KC; kc++) {
                if (kc + 1 < HID / KC) {
                    stage_act(xbufS + ((kc + 1) & 1) * 64 * SA, hsrc, (kc + 1) * KC, tid);
                    cp_commit();
                    cp_wait<1>();
                } else cp_wait<0>();
                __syncthreads();
                const unsigned xd = (kc & 1) ? XB1 : 0;
                #pragma unroll
                for (int j = 0; j < 2; j++) {
                    const int k16 = ks + j * 4;
                    unsigned a0[2][4], b0[2][4];
                    #pragma unroll
                    for (int mf = 0; mf < 2; mf++)
                        ldsm_x4(a0[mf][0], a0[mf][1], a0[mf][2], a0[mf][3],
                                xbA0[mf] + xd + k16 * 32);
                    #pragma unroll
                    for (int cg = 0; cg < 2; cg++)
                        ldsm_x4(b0[cg][0], b0[cg][1], b0[cg][2], b0[cg][3],
                                whB[l][cg] + (kc * KC + k16 * 16) * 2);
                    #pragma unroll
                    for (int mf = 0; mf < 2; mf++)
                        #pragma unroll
                        for (int cg = 0; cg < 2; cg++) {
                            hmma(acc[mf][cg * 2 + 0], a0[mf][0], a0[mf][1], a0[mf][2], a0[mf][3],
                                 b0[cg][0], b0[cg][2]);
                            hmma(acc[mf][cg * 2 + 1], a0[mf][0], a0[mf][1], a0[mf][2], a0[mf][3],
                                 b0[cg][1], b0[cg][3]);
                        }
                }
                __syncthreads();
            }

            // ===== barrier wait (mostly satisfied already) =====
            gbar_wait(barTarget);

            // ===== part B: x @ Wih (streamed) + FC (uniform k-split) =====
            stage_act(xbufS, xsrc, 0, tid);
            cp_commit();
            #pragma unroll 1
            for (int kc = 0; kc < HID / KC; kc++) {
                if (kc + 1 < HID / KC) {
                    stage_act(xbufS + ((kc + 1) & 1) * 64 * SA, xsrc, (kc + 1) * KC, tid);
                    stage_w(wbufS + ((kc + 1) & 1) * 32 * SW, wsrc, (kc + 1) * KC, tid);
                    cp_commit();
                    cp_wait<1>();
                } else cp_wait<0>();
                __syncthreads();
                const unsigned xd = (kc & 1) ? XB1 : 0;
                const unsigned wd = (kc & 1) ? WB1 : 0;
                #pragma unroll
                for (int j = 0; j < 2; j++) {
                    const int k16 = ks + j * 4;
                    unsigned a0[2][4], b0[2][4];
                    #pragma unroll
                    for (int mf = 0; mf < 2; mf++)
                        ldsm_x4(a0[mf][0], a0[mf][1], a0[mf][2], a0[mf][3],
                                xbA0[mf] + xd + k16 * 32);
                    #pragma unroll
                    for (int cg = 0; cg < 2; cg++)
                        ldsm_x4(b0[cg][0], b0[cg][1], b0[cg][2], b0[cg][3],
                                wbB0[cg] + wd + k16 * 32);
                    #pragma unroll
                    for (int mf = 0; mf < 2; mf++)
                        #pragma unroll
                        for (int cg = 0; cg < 2; cg++) {
                            hmma(acc[mf][cg * 2 + 0], a0[mf][0], a0[mf][1], a0[mf][2], a0[mf][3],
                                 b0[cg][0], b0[cg][2]);
                            hmma(acc[mf][cg * 2 + 1], a0[mf][0], a0[mf][1], a0[mf][2], a0[mf][3],
                                 b0[cg][1], b0[cg][3]);
                        }
                    if (fc_phase) {
                        unsigned f0, f1;
                        ldsm_x2(f0, f1, fcA + (kc * KC + k16 * 16) * 2);
                        #pragma unroll
                        for (int mf = 0; mf < 2; mf++)
                            hmma(fca[mf], a0[mf][0], a0[mf][1], a0[mf][2], a0[mf][3], f0, f1);
                    }
                }
                __syncthreads();
            }

            // ===== epilogue: 4-way k-split reduce through xbufS scratch =====
            if (ks > 0) {
                float* sp = xscr + (((ks - 1) * 2 + m2) * 32 + lane) * 40;
                #pragma unroll
                for (int mf = 0; mf < 2; mf++)
                    #pragma unroll
                    for (int nf = 0; nf < 4; nf++)
                        #pragma unroll
                        for (int c2 = 0; c2 < 4; c2++)
                            sp[(mf * 4 + nf) * 4 + c2] = acc[mf][nf][c2];
                #pragma unroll
                for (int mf = 0; mf < 2; mf++)
                    #pragma unroll
                    for (int c2 = 0; c2 < 4; c2++)
                        sp[32 + mf * 4 + c2] = fca[mf][c2];
            }
            __syncthreads();
            if (ks == 0) {
                #pragma unroll
                for (int sl = 0; sl < 3; sl++) {
                    const float* sp = xscr + ((sl * 2 + m2) * 32 + lane) * 40;
                    #pragma unroll
                    for (int mf = 0; mf < 2; mf++)
                        #pragma unroll
                        for (int nf = 0; nf < 4; nf++)
                            #pragma unroll
                            for (int c2 = 0; c2 < 4; c2++)
                                acc[mf][nf][c2] += sp[(mf * 4 + nf) * 4 + c2];
                    #pragma unroll
                    for (int mf = 0; mf < 2; mf++)
                        #pragma unroll
                        for (int c2 = 0; c2 < 4; c2++)
                            fca[mf][c2] += sp[32 + mf * 4 + c2];
                }

                float* crow = cS + l * 64 * 8;
                float* op = out + (size_t)(t - 1) * BATCH * HID;
                #pragma unroll
                for (int mf = 0; mf < 2; mf++) {
                    #pragma unroll
                    for (int rp = 0; rp < 2; rp++) {
                        const int b = m2 * 32 + mf * 16 + r + rp * 8;
                        const int k = rp * 2;
                        #pragma unroll
                        for (int ug = 0; ug < 2; ug++) {
                            const int u = ug * 4 + a4;
                            float iv = acc[mf][ug * 2 + 0][k + 0] + biasS[l * 32 + ug * 16 + a4 * 2 + 0];
                            float fv = acc[mf][ug * 2 + 0][k + 1] + biasS[l * 32 + ug * 16 + a4 * 2 + 1];
                            float gv = acc[mf][ug * 2 + 1][k + 0] + biasS[l * 32 + ug * 16 + 8 + a4 * 2 + 0];
                            float ov = acc[mf][ug * 2 + 1][k + 1] + biasS[l * 32 + ug * 16 + 8 + a4 * 2 + 1];
                            float cn = sig_(fv) * crow[b * 8 + u] + sig_(iv) * tanhf(gv);
                            crow[b * 8 + u] = cn;
                            hdst[b * HID + j0 + u] = __float2half_rn(sig_(ov) * tanhf(cn));
                        }
                        if (fc_phase) {
                            op[b * HID + j0 + a4 * 2 + 0] = fca[mf][k + 0] + fcbS[a4 * 2 + 0];
                            op[b * HID + j0 + a4 * 2 + 1] = fca[mf][k + 1] + fcbS[a4 * 2 + 1];
                        }
                    }
                }
            }
            gbar_arrive();
            barTarget += NCTA;
        }
    }

    // ===== final FC for t = T-1 (x = h1 written at t=127, parity 1) =====
    {
        gbar_wait(barTarget);
        const __half* xsrc = g_hbuf + (2 + 1) * BATCH * HID;
        float fca[2][4] = {{0,0,0,0},{0,0,0,0}};
        stage_act(xbufS, xsrc, 0, tid);
        cp_commit();
        #pragma unroll 1
        for (int kc = 0; kc < HID / KC; kc++) {
            if (kc + 1 < HID / KC) {
                stage_act(xbufS + ((kc + 1) & 1) * 64 * SA, xsrc, (kc + 1) * KC, tid);
                cp_commit();
                cp_wait<1>();
            } else cp_wait<0>();
            __syncthreads();
            const unsigned xd = (kc & 1) ? XB1 : 0;
            #pragma unroll
            for (int j = 0; j < 2; j++) {
                const int k16 = ks + j * 4;
                unsigned f0, f1;
                ldsm_x2(f0, f1, fcA + (kc * KC + k16 * 16) * 2);
                #pragma unroll
                for (int mf = 0; mf < 2; mf++) {
                    unsigned a0, a1, a2, a3;
                    ldsm_x4(a0, a1, a2, a3, xbA0[mf] + xd + k16 * 32);
                    hmma(fca[mf], a0, a1, a2, a3, f0, f1);
                }
            }
            __syncthreads();
        }
        if (ks > 0) {
            float* sp = xscr + (((ks - 1) * 2 + m2) * 32 + lane) * 40;
            #pragma unroll
            for (int mf = 0; mf < 2; mf++)
                #pragma unroll
                for (int c2 = 0; c2 < 4; c2++)
                    sp[32 + mf * 4 + c2] = fca[mf][c2];
        }
        __syncthreads();
        if (ks == 0) {
            #pragma unroll
            for (int sl = 0; sl < 3; sl++) {
                const float* sp = xscr + ((sl * 2 + m2) * 32 + lane) * 40;
                #pragma unroll
                for (int mf = 0; mf < 2; mf++)
                    #pragma unroll
                    for (int c2 = 0; c2 < 4; c2++)
                        fca[mf][c2] += sp[32 + mf * 4 + c2];
            }
            float* op = out + (size_t)(TSTEPS - 1) * BATCH * HID;
            #pragma unroll
            for (int mf = 0; mf < 2; mf++)
                #pragma unroll
                for (int rp = 0; rp < 2; rp++) {
                    const int b = m2 * 32 + mf * 16 + r + rp * 8;
                    const int k = rp * 2;
                    op[b * HID + j0 + a4 * 2 + 0] = fca[mf][k + 0] + fcbS[a4 * 2 + 0];
                    op[b * HID + j0 + a4 * 2 + 1] = fca[mf][k + 1] + fcbS[a4 * 2 + 1];
                }
        }
    }
}

// ---------------- host launch -----------------------------------------------
extern "C" void kernel_launch(void* const* d_in, const int* in_sizes, int n_in,
                              void* d_out, int out_size) {
    const float* h0  = (const float*)d_in[0];
    const float* Wih = (const float*)d_in[1];
    const float* Whh = (const float*)d_in[2];
    const float* bih = (const float*)d_in[3];
    const float* bhh = (const float*)d_in[4];
    const float* Wfc = (const float*)d_in[5];
    const float* bfc = (const float*)d_in[6];
    float* out = (float*)d_out;

    const int smem = (2 * 32 * SR + 8 * SR + 2 * 64 * SA + 2 * 32 * SW) * 2
                   + (2 * 64 * 8 + 64 + 8) * 4;
    cudaFuncSetAttribute(lstm_persist, cudaFuncAttributeMaxDynamicSharedMemorySize, smem);

    prep_all<<<2048, 256>>>(Wih, Whh, h0, Wfc);
    lstm_persist<<<NCTA, THREADS, smem>>>(bih, bhh, bfc, out);
}

// round 10
// speedup vs baseline: 1.5549x; 1.0253x over previous
#include <cuda_runtime.h>
#include <cuda_fp16.h>
#include <math.h>

// Persistent-kernel LSTM decoder. B=64, H=1024, L=2, T=128.
// 128 CTAs (1/SM), 256 threads (8 warps). R9 tiling: warp=(ks,m2),
// 32x32 tile over k16s {ks, ks+4}; 4-way k-split epilogue reduce.
// R10: ring-3 / prefetch-depth-2 cp.async pipeline at KC=128 with ONE
// __syncthreads per chunk. FC weights streamed with Wih (40-row B panel)
// to free SMEM for the third act buffer.

#define BATCH   64
#define HID     1024
#define TSTEPS  128
#define NCTA    128
#define THREADS 256
#define SA      136    // streamed act row stride (halfs)
#define SW      136    // streamed weight row stride (halfs)
#define SR      1032   // resident weight row stride (halfs)
#define KC      128    // K chunk
#define NKC     8      // chunks per matrix

// ---------------- device globals (pre-permuted fp16 weights + state) -------
__device__ __half g_Wst[2 * NCTA * 40 * HID];     // [l][cta][40 rows][k]: 32 gate + 8 FC
__device__ __half g_Whh_p[2 * NCTA * 32 * HID];   // resident recurrent weights
__device__ __half g_hbuf[4 * BATCH * HID];        // [l*2+parity][b][h]
__device__ __half g_x0[BATCH * HID];
__device__ unsigned g_bar;

// ---------------- small asm helpers ---------------------------------------
__device__ __forceinline__ unsigned sptr(const void* p) {
    return (unsigned)__cvta_generic_to_shared(p);
}
__device__ __forceinline__ void cp16(void* s, const void* g) {      // weights (.ca)
    asm volatile("cp.async.ca.shared.global [%0], [%1], 16;" :: "r"(sptr(s)), "l"(g));
}
__device__ __forceinline__ void cp16cg(void* s, const void* g) {    // acts (.cg)
    asm volatile("cp.async.cg.shared.global [%0], [%1], 16;" :: "r"(sptr(s)), "l"(g));
}
__device__ __forceinline__ void cp_commit() {
    asm volatile("cp.async.commit_group;");
}
template<int N> __device__ __forceinline__ void cp_wait() {
    asm volatile("cp.async.wait_group %0;" :: "n"(N));
}
__device__ __forceinline__ void ldsm_x4(unsigned &r0, unsigned &r1, unsigned &r2, unsigned &r3, unsigned a) {
    asm volatile("ldmatrix.sync.aligned.m8n8.x4.shared.b16 {%0,%1,%2,%3}, [%4];"
                 : "=r"(r0), "=r"(r1), "=r"(r2), "=r"(r3) : "r"(a));
}
__device__ __forceinline__ void ldsm_x2(unsigned &r0, unsigned &r1, unsigned a) {
    asm volatile("ldmatrix.sync.aligned.m8n8.x2.shared.b16 {%0,%1}, [%2];"
                 : "=r"(r0), "=r"(r1) : "r"(a));
}
__device__ __forceinline__ void hmma(float d[4], unsigned a0, unsigned a1, unsigned a2, unsigned a3,
                                     unsigned b0, unsigned b1) {
    asm volatile("mma.sync.aligned.m16n8k16.row.col.f32.f16.f16.f32 "
                 "{%0,%1,%2,%3},{%4,%5,%6,%7},{%8,%9},{%0,%1,%2,%3};"
                 : "+f"(d[0]), "+f"(d[1]), "+f"(d[2]), "+f"(d[3])
                 : "r"(a0), "r"(a1), "r"(a2), "r"(a3), "r"(b0), "r"(b1));
}
__device__ __forceinline__ float sig_(float x) { return 1.0f / (1.0f + __expf(-x)); }

// ---------------- single merged prep kernel ---------------------------------
// permuted col index pn -> (gate, unit):
//   nn=pn&15; half=nn>>3; a=(nn&7)>>1; s=nn&1; gate=half*2+s; unit=(pn>>4)*4+a
__global__ void prep_all(const float* __restrict__ Wih, const float* __restrict__ Whh,
                         const float* __restrict__ h0,  const float* __restrict__ Wfc) {
    int i = blockIdx.x * blockDim.x + threadIdx.x;
    int stride = gridDim.x * blockDim.x;
    const int totalG = 2 * NCTA * 32 * HID;
    for (int e = i; e < totalG; e += stride) {
        int k = e & (HID - 1);
        int pn = (e >> 10) & 31;
        int cta = (e >> 15) & (NCTA - 1);
        int l = e >> 22;
        int nn = pn & 15, half = nn >> 3, a = (nn & 7) >> 1, s = nn & 1;
        int gate = half * 2 + s, unit = (pn >> 4) * 4 + a;
        size_t src = (size_t)l * 4 * HID * HID + (size_t)(gate * HID + cta * 8 + unit) * HID + k;
        g_Whh_p[e] = __float2half_rn(Whh[src]);
        g_Wst[(size_t)((l * NCTA + cta) * 40 + pn) * HID + k] = __float2half_rn(Wih[src]);
    }
    const int totalF = 2 * NCTA * 8 * HID;
    for (int e = i; e < totalF; e += stride) {
        int k = e & (HID - 1);
        int u = (e >> 10) & 7;
        int cta = (e >> 13) & (NCTA - 1);
        int l = e >> 20;
        g_Wst[(size_t)((l * NCTA + cta) * 40 + 32 + u) * HID + k] =
            __float2half_rn(Wfc[(size_t)(cta * 8 + u) * HID + k]);
    }
    for (int e = i; e < BATCH * HID; e += stride) g_x0[e] = __float2half_rn(h0[e]);
    for (int e = i; e < 4 * BATCH * HID; e += stride) g_hbuf[e] = __float2half_rn(0.0f);
    if (i == 0) g_bar = 0;
}

// ---------------- split grid barrier ---------------------------------------
__device__ __forceinline__ void gbar_arrive() {
    __threadfence();
    __syncthreads();
    if (threadIdx.x == 0) atomicAdd(&g_bar, 1u);
}
__device__ __forceinline__ void gbar_wait(unsigned target) {
    if (threadIdx.x == 0) {
        unsigned v;
        do {
            asm volatile("ld.acquire.gpu.u32 %0, [%1];" : "=r"(v) : "l"(&g_bar));
        } while (v < target);
    }
    __syncthreads();
}

// ---------------- staging ---------------------------------------------------
__device__ __forceinline__ void stage_act(__half* dst, const __half* src, int k0, int tid) {
    #pragma unroll
    for (int i = 0; i < 4; i++) {
        int e = tid + i * THREADS;          // 1024 ops: 64 rows x 16 segs
        int r = e >> 4, sg = e & 15;
        cp16cg(dst + r * SA + sg * 8, src + r * HID + k0 + sg * 8);
    }
}
__device__ __forceinline__ void stage_w40(__half* dst, const __half* src, int k0, int tid) {
    #pragma unroll
    for (int i = 0; i < 3; i++) {
        int e = tid + i * THREADS;          // 640 ops: 40 rows x 16 segs
        if (e < 640) {
            int r = e >> 4, sg = e & 15;
            cp16(dst + r * SW + sg * 8, src + r * HID + k0 + sg * 8);
        }
    }
}

// ---------------- main persistent kernel ------------------------------------
__global__ __launch_bounds__(THREADS, 1) void lstm_persist(
    const float* __restrict__ bih, const float* __restrict__ bhh,
    const float* __restrict__ bfc, float* __restrict__ out)
{
    extern __shared__ __align__(16) unsigned char smem_raw[];
    __half* whhS  = (__half*)smem_raw;            // [2][32][SR]
    __half* xbufS = whhS + 2 * 32 * SR;           // [3][64][SA] act ring (+ epi scratch)
    __half* wbufS = xbufS + 3 * 64 * SA;          // [3][40][SW] streamed-W ring
    float*  cS    = (float*)(wbufS + 3 * 40 * SW);// [2][64][8]
    float*  biasS = cS + 2 * 64 * 8;              // [2][32]
    float*  fcbS  = biasS + 64;                   // [8]
    float*  xscr  = (float*)xbufS;                // epilogue reduce scratch

    const int tid  = threadIdx.x;
    const int warp = tid >> 5;
    const int lane = tid & 31;
    const int m2   = warp & 1;     // 32-row M half
    const int ks   = warp >> 1;    // k16 split (k16 in {ks, ks+4})
    const int cta  = blockIdx.x;
    const int j0   = cta * 8;

    const unsigned ABUF = 64 * SA * 2;   // act buffer stride (bytes)
    const unsigned WBUF = 40 * SW * 2;   // W buffer stride (bytes)

    // ---- load resident Whh (both layers) ----
    for (int l = 0; l < 2; l++) {
        const __half* src = g_Whh_p + (size_t)(l * NCTA + cta) * 32 * HID;
        for (int i = 0; i < 16; i++) {
            int e = tid + i * THREADS;      // 32 rows x 128 segs
            int r = e >> 7, sg = e & 127;
            cp16(whhS + l * 32 * SR + r * SR + sg * 8, src + r * HID + sg * 8);
        }
    }
    cp_commit();
    // ---- biases / cell state ----
    if (tid < 64) {
        int l = tid >> 5, pn = tid & 31;
        int nn = pn & 15, half = nn >> 3, a = (nn & 7) >> 1, s = nn & 1;
        int gate = half * 2 + s, unit = (pn >> 4) * 4 + a;
        int row = gate * HID + j0 + unit;
        biasS[l * 32 + pn] = bih[l * 4 * HID + row] + bhh[l * 4 * HID + row];
    }
    if (tid < 8) fcbS[tid] = bfc[j0 + tid];
    #pragma unroll
    for (int i = 0; i < 4; i++) cS[tid + i * THREADS] = 0.0f;
    cp_wait<0>();
    __syncthreads();

    // per-lane fragment addresses (bytes; ring delta added per chunk)
    const unsigned xbA0[2] = {
        sptr(xbufS) + ((m2 * 32 + 0  + (lane & 15)) * SA + (lane >> 4) * 8) * 2,
        sptr(xbufS) + ((m2 * 32 + 16 + (lane & 15)) * SA + (lane >> 4) * 8) * 2 };
    const unsigned wbB0[2] = {
        sptr(wbufS) + ((0  + (lane & 15)) * SW + (lane >> 4) * 8) * 2,
        sptr(wbufS) + ((16 + (lane & 15)) * SW + (lane >> 4) * 8) * 2 };
    const unsigned fcB0 =
        sptr(wbufS) + ((32 + (lane & 7)) * SW + ((lane >> 3) & 1) * 8) * 2;
    const unsigned whB[2][2] = {
        { sptr(whhS) + ((0  + (lane & 15)) * SR + (lane >> 4) * 8) * 2,
          sptr(whhS) + ((16 + (lane & 15)) * SR + (lane >> 4) * 8) * 2 },
        { sptr(whhS) + ((32 + 0  + (lane & 15)) * SR + (lane >> 4) * 8) * 2,
          sptr(whhS) + ((32 + 16 + (lane & 15)) * SR + (lane >> 4) * 8) * 2 } };

    unsigned barTarget = 0;
    const int r = lane >> 2, a4 = lane & 3;

    for (int t = 0; t < TSTEPS; t++) {
        const int p = t & 1, q = p ^ 1;
        #pragma unroll 1
        for (int l = 0; l < 2; l++) {
            const __half* xsrc = (l == 0)
                ? ((t == 0) ? g_x0 : g_hbuf + (2 + q) * BATCH * HID)
                : g_hbuf + (0 + p) * BATCH * HID;
            const __half* hsrc = g_hbuf + (l * 2 + q) * BATCH * HID;
            __half* hdst = g_hbuf + (l * 2 + p) * BATCH * HID;
            const __half* wsrc = g_Wst + (size_t)(l * NCTA + cta) * 40 * HID;
            const bool fc_phase = (l == 0) && (t > 0);

            float acc[2][4][4];                 // [mf][nf][frag]
            #pragma unroll
            for (int a = 0; a < 2; a++)
                #pragma unroll
                for (int b = 0; b < 4; b++)
                    #pragma unroll
                    for (int c2 = 0; c2 < 4; c2++) acc[a][b][c2] = 0.0f;
            float fca[2][4] = {{0,0,0,0},{0,0,0,0}};

            // ===== part A: h_rec @ Whh (resident; hsrc written 2 phases ago)
            stage_act(xbufS, hsrc, 0, tid); cp_commit();
            stage_act(xbufS + 64 * SA, hsrc, KC, tid); cp_commit();
            #pragma unroll 1
            for (int kc = 0; kc < NKC; kc++) {
                cp_wait<1>();
                __syncthreads();
                if (kc + 2 < NKC)
                    stage_act(xbufS + ((kc + 2) % 3) * 64 * SA, hsrc, (kc + 2) * KC, tid);
                cp_commit();
                const unsigned xd = (kc % 3) * ABUF;
                #pragma unroll
                for (int j = 0; j < 2; j++) {
                    const int k16 = ks + j * 4;
                    unsigned a0[2][4], b0[2][4];
                    #pragma unroll
                    for (int mf = 0; mf < 2; mf++)
                        ldsm_x4(a0[mf][0], a0[mf][1], a0[mf][2], a0[mf][3],
                                xbA0[mf] + xd + k16 * 32);
                    #pragma unroll
                    for (int cg = 0; cg < 2; cg++)
                        ldsm_x4(b0[cg][0], b0[cg][1], b0[cg][2], b0[cg][3],
                                whB[l][cg] + (kc * KC + k16 * 16) * 2);
                    #pragma unroll
                    for (int mf = 0; mf < 2; mf++)
                        #pragma unroll
                        for (int cg = 0; cg < 2; cg++) {
                            hmma(acc[mf][cg * 2 + 0], a0[mf][0], a0[mf][1], a0[mf][2], a0[mf][3],
                                 b0[cg][0], b0[cg][2]);
                            hmma(acc[mf][cg * 2 + 1], a0[mf][0], a0[mf][1], a0[mf][2], a0[mf][3],
                                 b0[cg][1], b0[cg][3]);
                        }
                }
            }

            // ===== barrier wait (mostly satisfied already) =====
            gbar_wait(barTarget);

            // ===== part B: x @ [Wih | Wfc] streamed, gates + FC ============
            stage_act(xbufS, xsrc, 0, tid);
            stage_w40(wbufS, wsrc, 0, tid); cp_commit();
            stage_act(xbufS + 64 * SA, xsrc, KC, tid);
            stage_w40(wbufS + 40 * SW, wsrc, KC, tid); cp_commit();
            #pragma unroll 1
            for (int kc = 0; kc < NKC; kc++) {
                cp_wait<1>();
                __syncthreads();
                if (kc + 2 < NKC) {
                    stage_act(xbufS + ((kc + 2) % 3) * 64 * SA, xsrc, (kc + 2) * KC, tid);
                    stage_w40(wbufS + ((kc + 2) % 3) * 40 * SW, wsrc, (kc + 2) * KC, tid);
                }
                cp_commit();
                const unsigned xd = (kc % 3) * ABUF;
                const unsigned wd = (kc % 3) * WBUF;
                #pragma unroll
                for (int j = 0; j < 2; j++) {
                    const int k16 = ks + j * 4;
                    unsigned a0[2][4], b0[2][4];
                    #pragma unroll
                    for (int mf = 0; mf < 2; mf++)
                        ldsm_x4(a0[mf][0], a0[mf][1], a0[mf][2], a0[mf][3],
                                xbA0[mf] + xd + k16 * 32);
                    #pragma unroll
                    for (int cg = 0; cg < 2; cg++)
                        ldsm_x4(b0[cg][0], b0[cg][1], b0[cg][2], b0[cg][3],
                                wbB0[cg] + wd + k16 * 32);
                    #pragma unroll
                    for (int mf = 0; mf < 2; mf++)
                        #pragma unroll
                        for (int cg = 0; cg < 2; cg++) {
                            hmma(acc[mf][cg * 2 + 0], a0[mf][0], a0[mf][1], a0[mf][2], a0[mf][3],
                                 b0[cg][0], b0[cg][2]);
                            hmma(acc[mf][cg * 2 + 1], a0[mf][0], a0[mf][1], a0[mf][2], a0[mf][3],
                                 b0[cg][1], b0[cg][3]);
                        }
                    if (fc_phase) {
                        unsigned f0, f1;
                        ldsm_x2(f0, f1, fcB0 + wd + k16 * 32);
                        #pragma unroll
                        for (int mf = 0; mf < 2; mf++)
                            hmma(fca[mf], a0[mf][0], a0[mf][1], a0[mf][2], a0[mf][3], f0, f1);
                    }
                }
            }

            // ===== epilogue: 4-way k-split reduce through xbufS scratch =====
            __syncthreads();           // all compute done before scratch reuse
            if (ks > 0) {
                float* sp = xscr + (((ks - 1) * 2 + m2) * 32 + lane) * 40;
                #pragma unroll
                for (int mf = 0; mf < 2; mf++)
                    #pragma unroll
                    for (int nf = 0; nf < 4; nf++)
                        #pragma unroll
                        for (int c2 = 0; c2 < 4; c2++)
                            sp[(mf * 4 + nf) * 4 + c2] = acc[mf][nf][c2];
                #pragma unroll
                for (int mf = 0; mf < 2; mf++)
                    #pragma unroll
                    for (int c2 = 0; c2 < 4; c2++)
                        sp[32 + mf * 4 + c2] = fca[mf][c2];
            }
            __syncthreads();
            if (ks == 0) {
                #pragma unroll
                for (int sl = 0; sl < 3; sl++) {
                    const float* sp = xscr + ((sl * 2 + m2) * 32 + lane) * 40;
                    #pragma unroll
                    for (int mf = 0; mf < 2; mf++)
                        #pragma unroll
                        for (int nf = 0; nf < 4; nf++)
                            #pragma unroll
                            for (int c2 = 0; c2 < 4; c2++)
                                acc[mf][nf][c2] += sp[(mf * 4 + nf) * 4 + c2];
                    #pragma unroll
                    for (int mf = 0; mf < 2; mf++)
                        #pragma unroll
                        for (int c2 = 0; c2 < 4; c2++)
                            fca[mf][c2] += sp[32 + mf * 4 + c2];
                }

                float* crow = cS + l * 64 * 8;
                float* op = out + (size_t)(t - 1) * BATCH * HID;
                #pragma unroll
                for (int mf = 0; mf < 2; mf++) {
                    #pragma unroll
                    for (int rp = 0; rp < 2; rp++) {
                        const int b = m2 * 32 + mf * 16 + r + rp * 8;
                        const int k = rp * 2;
                        #pragma unroll
                        for (int ug = 0; ug < 2; ug++) {
                            const int u = ug * 4 + a4;
                            float iv = acc[mf][ug * 2 + 0][k + 0] + biasS[l * 32 + ug * 16 + a4 * 2 + 0];
                            float fv = acc[mf][ug * 2 + 0][k + 1] + biasS[l * 32 + ug * 16 + a4 * 2 + 1];
                            float gv = acc[mf][ug * 2 + 1][k + 0] + biasS[l * 32 + ug * 16 + 8 + a4 * 2 + 0];
                            float ov = acc[mf][ug * 2 + 1][k + 1] + biasS[l * 32 + ug * 16 + 8 + a4 * 2 + 1];
                            float cn = sig_(fv) * crow[b * 8 + u] + sig_(iv) * tanhf(gv);
                            crow[b * 8 + u] = cn;
                            hdst[b * HID + j0 + u] = __float2half_rn(sig_(ov) * tanhf(cn));
                        }
                        if (fc_phase) {
                            op[b * HID + j0 + a4 * 2 + 0] = fca[mf][k + 0] + fcbS[a4 * 2 + 0];
                            op[b * HID + j0 + a4 * 2 + 1] = fca[mf][k + 1] + fcbS[a4 * 2 + 1];
                        }
                    }
                }
            }
            gbar_arrive();
            barTarget += NCTA;
        }
    }

    // ===== final FC for t = T-1 (x = h1 written at t=127, parity 1) =====
    {
        gbar_wait(barTarget);
        const __half* xsrc = g_hbuf + (2 + 1) * BATCH * HID;
        const __half* wsrc = g_Wst + (size_t)(0 * NCTA + cta) * 40 * HID;
        float fca[2][4] = {{0,0,0,0},{0,0,0,0}};
        stage_act(xbufS, xsrc, 0, tid);
        stage_w40(wbufS, wsrc, 0, tid); cp_commit();
        stage_act(xbufS + 64 * SA, xsrc, KC, tid);
        stage_w40(wbufS + 40 * SW, wsrc, KC, tid); cp_commit();
        #pragma unroll 1
        for (int kc = 0; kc < NKC; kc++) {
            cp_wait<1>();
            __syncthreads();
            if (kc + 2 < NKC) {
                stage_act(xbufS + ((kc + 2) % 3) * 64 * SA, xsrc, (kc + 2) * KC, tid);
                stage_w40(wbufS + ((kc + 2) % 3) * 40 * SW, wsrc, (kc + 2) * KC, tid);
            }
            cp_commit();
            const unsigned xd = (kc % 3) * ABUF;
            const unsigned wd = (kc % 3) * WBUF;
            #pragma unroll
            for (int j = 0; j < 2; j++) {
                const int k16 = ks + j * 4;
                unsigned f0, f1;
                ldsm_x2(f0, f1, fcB0 + wd + k16 * 32);
                #pragma unroll
                for (int mf = 0; mf < 2; mf++) {
                    unsigned a0, a1, a2, a3;
                    ldsm_x4(a0, a1, a2, a3, xbA0[mf] + xd + k16 * 32);
                    hmma(fca[mf], a0, a1, a2, a3, f0, f1);
                }
            }
        }
        __syncthreads();
        if (ks > 0) {
            float* sp = xscr + (((ks - 1) * 2 + m2) * 32 + lane) * 40;
            #pragma unroll
            for (int mf = 0; mf < 2; mf++)
                #pragma unroll
                for (int c2 = 0; c2 < 4; c2++)
                    sp[32 + mf * 4 + c2] = fca[mf][c2];
        }
        __syncthreads();
        if (ks == 0) {
            #pragma unroll
            for (int sl = 0; sl < 3; sl++) {
                const float* sp = xscr + ((sl * 2 + m2) * 32 + lane) * 40;
                #pragma unroll
                for (int mf = 0; mf < 2; mf++)
                    #pragma unroll
                    for (int c2 = 0; c2 < 4; c2++)
                        fca[mf][c2] += sp[32 + mf * 4 + c2];
            }
            float* op = out + (size_t)(TSTEPS - 1) * BATCH * HID;
            #pragma unroll
            for (int mf = 0; mf < 2; mf++)
                #pragma unroll
                for (int rp = 0; rp < 2; rp++) {
                    const int b = m2 * 32 + mf * 16 + r + rp * 8;
                    const int k = rp * 2;
                    op[b * HID + j0 + a4 * 2 + 0] = fca[mf][k + 0] + fcbS[a4 * 2 + 0];
                    op[b * HID + j0 + a4 * 2 + 1] = fca[mf][k + 1] + fcbS[a4 * 2 + 1];
                }
        }
    }
}

// ---------------- host launch -----------------------------------------------
extern "C" void kernel_launch(void* const* d_in, const int* in_sizes, int n_in,
                              void* d_out, int out_size) {
    const float* h0  = (const float*)d_in[0];
    const float* Wih = (const float*)d_in[1];
    const float* Whh = (const float*)d_in[2];
    const float* bih = (const float*)d_in[3];
    const float* bhh = (const float*)d_in[4];
    const float* Wfc = (const float*)d_in[5];
    const float* bfc = (const float*)d_in[6];
    float* out = (float*)d_out;

    const int smem = (2 * 32 * SR + 3 * 64 * SA + 3 * 40 * SW) * 2
                   + (2 * 64 * 8 + 64 + 8) * 4;
    cudaFuncSetAttribute(lstm_persist, cudaFuncAttributeMaxDynamicSharedMemorySize, smem);

    prep_all<<<2048, 256>>>(Wih, Whh, h0, Wfc);
    lstm_persist<<<NCTA, THREADS, smem>>>(bih, bhh, bfc, out);
}

// round 11
// speedup vs baseline: 1.6687x; 1.0732x over previous
#include <cuda_runtime.h>
#include <cuda_fp16.h>
#include <math.h>

// Persistent-kernel LSTM decoder. B=64, H=1024, L=2, T=128.
// 128 CTAs (1/SM), 256 threads (8 warps). R9/R10 tiling: warp=(ks,m2),
// 32x32 tile over k16s {ks, ks+4}; 4-way k-split epilogue reduce.
// R11: CONTINUOUS act ring across phase boundaries (next-phase part-A
// chunks prefetched during current part B / right after arrive), epilogue
// scratch moved to the consumed W ring, and release-atomic grid-barrier
// arrive (drops the full __threadfence MEMBAR drain).

#define BATCH   64
#define HID     1024
#define TSTEPS  128
#define NCTA    128
#define THREADS 256
#define SA      136    // streamed act row stride (halfs)
#define SW      136    // streamed weight row stride (halfs)
#define SR      1032   // resident weight row stride (halfs)
#define KC      128    // K chunk
#define NKC     8      // chunks per matrix
#define NX3(s)  (((s) + 1 == 3) ? 0 : (s) + 1)

// ---------------- device globals (pre-permuted fp16 weights + state) -------
__device__ __half g_Wst[2 * NCTA * 40 * HID];     // [l][cta][40 rows][k]: 32 gate + 8 FC
__device__ __half g_Whh_p[2 * NCTA * 32 * HID];   // resident recurrent weights
__device__ __half g_hbuf[4 * BATCH * HID];        // [l*2+parity][b][h]
__device__ __half g_x0[BATCH * HID];
__device__ unsigned g_bar;

// ---------------- small asm helpers ---------------------------------------
__device__ __forceinline__ unsigned sptr(const void* p) {
    return (unsigned)__cvta_generic_to_shared(p);
}
__device__ __forceinline__ void cp16(void* s, const void* g) {      // weights (.ca)
    asm volatile("cp.async.ca.shared.global [%0], [%1], 16;" :: "r"(sptr(s)), "l"(g));
}
__device__ __forceinline__ void cp16cg(void* s, const void* g) {    // acts (.cg)
    asm volatile("cp.async.cg.shared.global [%0], [%1], 16;" :: "r"(sptr(s)), "l"(g));
}
__device__ __forceinline__ void cp_commit() {
    asm volatile("cp.async.commit_group;");
}
template<int N> __device__ __forceinline__ void cp_wait() {
    asm volatile("cp.async.wait_group %0;" :: "n"(N));
}
__device__ __forceinline__ void ldsm_x4(unsigned &r0, unsigned &r1, unsigned &r2, unsigned &r3, unsigned a) {
    asm volatile("ldmatrix.sync.aligned.m8n8.x4.shared.b16 {%0,%1,%2,%3}, [%4];"
                 : "=r"(r0), "=r"(r1), "=r"(r2), "=r"(r3) : "r"(a));
}
__device__ __forceinline__ void ldsm_x2(unsigned &r0, unsigned &r1, unsigned a) {
    asm volatile("ldmatrix.sync.aligned.m8n8.x2.shared.b16 {%0,%1}, [%2];"
                 : "=r"(r0), "=r"(r1) : "r"(a));
}
__device__ __forceinline__ void hmma(float d[4], unsigned a0, unsigned a1, unsigned a2, unsigned a3,
                                     unsigned b0, unsigned b1) {
    asm volatile("mma.sync.aligned.m16n8k16.row.col.f32.f16.f16.f32 "
                 "{%0,%1,%2,%3},{%4,%5,%6,%7},{%8,%9},{%0,%1,%2,%3};"
                 : "+f"(d[0]), "+f"(d[1]), "+f"(d[2]), "+f"(d[3])
                 : "r"(a0), "r"(a1), "r"(a2), "r"(a3), "r"(b0), "r"(b1));
}
__device__ __forceinline__ float sig_(float x) { return 1.0f / (1.0f + __expf(-x)); }

// ---------------- single merged prep kernel ---------------------------------
// permuted col index pn -> (gate, unit):
//   nn=pn&15; half=nn>>3; a=(nn&7)>>1; s=nn&1; gate=half*2+s; unit=(pn>>4)*4+a
__global__ void prep_all(const float* __restrict__ Wih, const float* __restrict__ Whh,
                         const float* __restrict__ h0,  const float* __restrict__ Wfc) {
    int i = blockIdx.x * blockDim.x + threadIdx.x;
    int stride = gridDim.x * blockDim.x;
    const int totalG = 2 * NCTA * 32 * HID;
    for (int e = i; e < totalG; e += stride) {
        int k = e & (HID - 1);
        int pn = (e >> 10) & 31;
        int cta = (e >> 15) & (NCTA - 1);
        int l = e >> 22;
        int nn = pn & 15, half = nn >> 3, a = (nn & 7) >> 1, s = nn & 1;
        int gate = half * 2 + s, unit = (pn >> 4) * 4 + a;
        size_t src = (size_t)l * 4 * HID * HID + (size_t)(gate * HID + cta * 8 + unit) * HID + k;
        g_Whh_p[e] = __float2half_rn(Whh[src]);
        g_Wst[(size_t)((l * NCTA + cta) * 40 + pn) * HID + k] = __float2half_rn(Wih[src]);
    }
    const int totalF = 2 * NCTA * 8 * HID;
    for (int e = i; e < totalF; e += stride) {
        int k = e & (HID - 1);
        int u = (e >> 10) & 7;
        int cta = (e >> 13) & (NCTA - 1);
        int l = e >> 20;
        g_Wst[(size_t)((l * NCTA + cta) * 40 + 32 + u) * HID + k] =
            __float2half_rn(Wfc[(size_t)(cta * 8 + u) * HID + k]);
    }
    for (int e = i; e < BATCH * HID; e += stride) g_x0[e] = __float2half_rn(h0[e]);
    for (int e = i; e < 4 * BATCH * HID; e += stride) g_hbuf[e] = __float2half_rn(0.0f);
    if (i == 0) g_bar = 0;
}

// ---------------- split grid barrier ---------------------------------------
__device__ __forceinline__ void gbar_arrive() {
    __syncthreads();
    if (threadIdx.x == 0)
        asm volatile("red.release.gpu.add.u32 [%0], %1;" :: "l"(&g_bar), "r"(1u) : "memory");
}
__device__ __forceinline__ void gbar_wait(unsigned target) {
    if (threadIdx.x == 0) {
        unsigned v;
        do {
            asm volatile("ld.acquire.gpu.u32 %0, [%1];" : "=r"(v) : "l"(&g_bar));
        } while (v < target);
    }
    __syncthreads();
}

// ---------------- staging ---------------------------------------------------
__device__ __forceinline__ void stage_act(__half* dst, const __half* src, int k0, int tid) {
    #pragma unroll
    for (int i = 0; i < 4; i++) {
        int e = tid + i * THREADS;          // 1024 ops: 64 rows x 16 segs
        int r = e >> 4, sg = e & 15;
        cp16cg(dst + r * SA + sg * 8, src + r * HID + k0 + sg * 8);
    }
}
__device__ __forceinline__ void stage_w40(__half* dst, const __half* src, int k0, int tid) {
    #pragma unroll
    for (int i = 0; i < 3; i++) {
        int e = tid + i * THREADS;          // 640 ops: 40 rows x 16 segs
        if (e < 640) {
            int r = e >> 4, sg = e & 15;
            cp16(dst + r * SW + sg * 8, src + r * HID + k0 + sg * 8);
        }
    }
}

// ---------------- main persistent kernel ------------------------------------
__global__ __launch_bounds__(THREADS, 1) void lstm_persist(
    const float* __restrict__ bih, const float* __restrict__ bhh,
    const float* __restrict__ bfc, float* __restrict__ out)
{
    extern __shared__ __align__(16) unsigned char smem_raw[];
    __half* whhS  = (__half*)smem_raw;            // [2][32][SR]
    __half* xbufS = whhS + 2 * 32 * SR;           // [3][64][SA] continuous act ring
    __half* wbufS = xbufS + 3 * 64 * SA;          // [3][40][SW] streamed-W ring (+ epi scratch)
    float*  cS    = (float*)(wbufS + 3 * 40 * SW);// [2][64][8]
    float*  biasS = cS + 2 * 64 * 8;              // [2][32]
    float*  fcbS  = biasS + 64;                   // [8]
    float*  wscr  = (float*)wbufS;                // epilogue reduce scratch

    const int tid  = threadIdx.x;
    const int warp = tid >> 5;
    const int lane = tid & 31;
    const int m2   = warp & 1;     // 32-row M half
    const int ks   = warp >> 1;    // k16 split (k16 in {ks, ks+4})
    const int cta  = blockIdx.x;
    const int j0   = cta * 8;

    const unsigned ABUF = 64 * SA * 2;   // act buffer stride (bytes)
    const unsigned WBUF = 40 * SW * 2;   // W buffer stride (bytes)
    const int ABUFH = 64 * SA;           // act buffer stride (halfs)
    const int WBUFH = 40 * SW;

    // ---- load resident Whh (both layers) ----
    for (int l = 0; l < 2; l++) {
        const __half* src = g_Whh_p + (size_t)(l * NCTA + cta) * 32 * HID;
        for (int i = 0; i < 16; i++) {
            int e = tid + i * THREADS;      // 32 rows x 128 segs
            int r = e >> 7, sg = e & 127;
            cp16(whhS + l * 32 * SR + r * SR + sg * 8, src + r * HID + sg * 8);
        }
    }
    cp_commit();
    // ---- biases / cell state ----
    if (tid < 64) {
        int l = tid >> 5, pn = tid & 31;
        int nn = pn & 15, half = nn >> 3, a = (nn & 7) >> 1, s = nn & 1;
        int gate = half * 2 + s, unit = (pn >> 4) * 4 + a;
        int row = gate * HID + j0 + unit;
        biasS[l * 32 + pn] = bih[l * 4 * HID + row] + bhh[l * 4 * HID + row];
    }
    if (tid < 8) fcbS[tid] = bfc[j0 + tid];
    #pragma unroll
    for (int i = 0; i < 4; i++) cS[tid + i * THREADS] = 0.0f;
    cp_wait<0>();
    __syncthreads();

    // per-lane fragment base addresses (slot-0; slot delta added at use)
    const unsigned xbA0[2] = {
        sptr(xbufS) + ((m2 * 32 + 0  + (lane & 15)) * SA + (lane >> 4) * 8) * 2,
        sptr(xbufS) + ((m2 * 32 + 16 + (lane & 15)) * SA + (lane >> 4) * 8) * 2 };
    const unsigned wbB0[2] = {
        sptr(wbufS) + ((0  + (lane & 15)) * SW + (lane >> 4) * 8) * 2,
        sptr(wbufS) + ((16 + (lane & 15)) * SW + (lane >> 4) * 8) * 2 };
    const unsigned fcB0 =
        sptr(wbufS) + ((32 + (lane & 7)) * SW + ((lane >> 3) & 1) * 8) * 2;
    const unsigned whB[2][2] = {
        { sptr(whhS) + ((0  + (lane & 15)) * SR + (lane >> 4) * 8) * 2,
          sptr(whhS) + ((16 + (lane & 15)) * SR + (lane >> 4) * 8) * 2 },
        { sptr(whhS) + ((32 + 0  + (lane & 15)) * SR + (lane >> 4) * 8) * 2,
          sptr(whhS) + ((32 + 16 + (lane & 15)) * SR + (lane >> 4) * 8) * 2 } };

    unsigned barTarget = 0;
    const int r = lane >> 2, a4 = lane & 3;

    // ring slot state (continuous across phases)
    int s_stage = 0, s_cons = 0;   // act ring
    int w_stage = 0, w_cons = 0;   // W ring

    // ---- prologue: stage part-A chunks 0,1 of the first phase ----
    {
        const __half* h00 = g_hbuf + (0 + 1) * BATCH * HID;   // t=0: q=1
        stage_act(xbufS + s_stage * ABUFH, h00, 0, tid); cp_commit(); s_stage = NX3(s_stage);
        stage_act(xbufS + s_stage * ABUFH, h00, KC, tid); cp_commit(); s_stage = NX3(s_stage);
    }

    for (int t = 0; t < TSTEPS; t++) {
        const int p = t & 1, q = p ^ 1;
        #pragma unroll 1
        for (int l = 0; l < 2; l++) {
            const __half* xsrc = (l == 0)
                ? ((t == 0) ? g_x0 : g_hbuf + (2 + q) * BATCH * HID)
                : g_hbuf + (0 + p) * BATCH * HID;
            const __half* hsrc = g_hbuf + (l * 2 + q) * BATCH * HID;
            __half* hdst = g_hbuf + (l * 2 + p) * BATCH * HID;
            const __half* wsrc = g_Wst + (size_t)(l * NCTA + cta) * 40 * HID;
            // next phase's part-A input (legal already: written >= 1 phase ago)
            const __half* nhsrc = (l == 0) ? g_hbuf + (2 + q) * BATCH * HID
                                           : g_hbuf + (0 + p) * BATCH * HID;
            const bool fc_phase = (l == 0) && (t > 0);
            const bool last_phase = (l == 1) && (t == TSTEPS - 1);

            float acc[2][4][4];
            #pragma unroll
            for (int a = 0; a < 2; a++)
                #pragma unroll
                for (int b = 0; b < 4; b++)
                    #pragma unroll
                    for (int c2 = 0; c2 < 4; c2++) acc[a][b][c2] = 0.0f;
            float fca[2][4] = {{0,0,0,0},{0,0,0,0}};

            // ===== part A: h_rec @ Whh (resident; chunks 0,1 already staged)
            #pragma unroll 1
            for (int kc = 0; kc < NKC; kc++) {
                cp_wait<1>();
                __syncthreads();
                if (kc + 2 < NKC) {
                    stage_act(xbufS + s_stage * ABUFH, hsrc, (kc + 2) * KC, tid);
                    s_stage = NX3(s_stage);
                }
                cp_commit();
                const unsigned xd = (unsigned)s_cons * ABUF;
                s_cons = NX3(s_cons);
                #pragma unroll
                for (int j = 0; j < 2; j++) {
                    const int k16 = ks + j * 4;
                    unsigned a0[2][4], b0[2][4];
                    #pragma unroll
                    for (int mf = 0; mf < 2; mf++)
                        ldsm_x4(a0[mf][0], a0[mf][1], a0[mf][2], a0[mf][3],
                                xbA0[mf] + xd + k16 * 32);
                    #pragma unroll
                    for (int cg = 0; cg < 2; cg++)
                        ldsm_x4(b0[cg][0], b0[cg][1], b0[cg][2], b0[cg][3],
                                whB[l][cg] + (kc * KC + k16 * 16) * 2);
                    #pragma unroll
                    for (int mf = 0; mf < 2; mf++)
                        #pragma unroll
                        for (int cg = 0; cg < 2; cg++) {
                            hmma(acc[mf][cg * 2 + 0], a0[mf][0], a0[mf][1], a0[mf][2], a0[mf][3],
                                 b0[cg][0], b0[cg][2]);
                            hmma(acc[mf][cg * 2 + 1], a0[mf][0], a0[mf][1], a0[mf][2], a0[mf][3],
                                 b0[cg][1], b0[cg][3]);
                        }
                }
            }

            // ===== barrier wait (mostly satisfied already) =====
            gbar_wait(barTarget);

            // ===== part B: x @ [Wih | Wfc] streamed =====
            #pragma unroll
            for (int i = 0; i < 2; i++) {
                stage_act(xbufS + s_stage * ABUFH, xsrc, i * KC, tid);
                stage_w40(wbufS + w_stage * WBUFH, wsrc, i * KC, tid);
                cp_commit();
                s_stage = NX3(s_stage); w_stage = NX3(w_stage);
            }
            #pragma unroll 1
            for (int kc = 0; kc < NKC; kc++) {
                cp_wait<1>();
                __syncthreads();
                if (kc + 2 < NKC) {
                    stage_act(xbufS + s_stage * ABUFH, xsrc, (kc + 2) * KC, tid);
                    stage_w40(wbufS + w_stage * WBUFH, wsrc, (kc + 2) * KC, tid);
                    s_stage = NX3(s_stage); w_stage = NX3(w_stage);
                } else if (kc == NKC - 2 && !last_phase) {
                    // prefetch next phase's part-A chunk 0
                    stage_act(xbufS + s_stage * ABUFH, nhsrc, 0, tid);
                    s_stage = NX3(s_stage);
                }
                cp_commit();
                const unsigned xd = (unsigned)s_cons * ABUF;
                const unsigned wd = (unsigned)w_cons * WBUF;
                s_cons = NX3(s_cons); w_cons = NX3(w_cons);
                #pragma unroll
                for (int j = 0; j < 2; j++) {
                    const int k16 = ks + j * 4;
                    unsigned a0[2][4], b0[2][4];
                    #pragma unroll
                    for (int mf = 0; mf < 2; mf++)
                        ldsm_x4(a0[mf][0], a0[mf][1], a0[mf][2], a0[mf][3],
                                xbA0[mf] + xd + k16 * 32);
                    #pragma unroll
                    for (int cg = 0; cg < 2; cg++)
                        ldsm_x4(b0[cg][0], b0[cg][1], b0[cg][2], b0[cg][3],
                                wbB0[cg] + wd + k16 * 32);
                    #pragma unroll
                    for (int mf = 0; mf < 2; mf++)
                        #pragma unroll
                        for (int cg = 0; cg < 2; cg++) {
                            hmma(acc[mf][cg * 2 + 0], a0[mf][0], a0[mf][1], a0[mf][2], a0[mf][3],
                                 b0[cg][0], b0[cg][2]);
                            hmma(acc[mf][cg * 2 + 1], a0[mf][0], a0[mf][1], a0[mf][2], a0[mf][3],
                                 b0[cg][1], b0[cg][3]);
                        }
                    if (fc_phase) {
                        unsigned f0, f1;
                        ldsm_x2(f0, f1, fcB0 + wd + k16 * 32);
                        #pragma unroll
                        for (int mf = 0; mf < 2; mf++)
                            hmma(fca[mf], a0[mf][0], a0[mf][1], a0[mf][2], a0[mf][3], f0, f1);
                    }
                }
            }

            // ===== epilogue: 4-way k-split reduce through wbufS scratch =====
            __syncthreads();           // all W-ring reads done before scratch reuse
            if (ks > 0) {
                float* sp = wscr + (((ks - 1) * 2 + m2) * 32 + lane) * 40;
                #pragma unroll
                for (int mf = 0; mf < 2; mf++)
                    #pragma unroll
                    for (int nf = 0; nf < 4; nf++)
                        #pragma unroll
                        for (int c2 = 0; c2 < 4; c2++)
                            sp[(mf * 4 + nf) * 4 + c2] = acc[mf][nf][c2];
                #pragma unroll
                for (int mf = 0; mf < 2; mf++)
                    #pragma unroll
                    for (int c2 = 0; c2 < 4; c2++)
                        sp[32 + mf * 4 + c2] = fca[mf][c2];
            }
            __syncthreads();
            if (ks == 0) {
                #pragma unroll
                for (int sl = 0; sl < 3; sl++) {
                    const float* sp = wscr + ((sl * 2 + m2) * 32 + lane) * 40;
                    #pragma unroll
                    for (int mf = 0; mf < 2; mf++)
                        #pragma unroll
                        for (int nf = 0; nf < 4; nf++)
                            #pragma unroll
                            for (int c2 = 0; c2 < 4; c2++)
                                acc[mf][nf][c2] += sp[(mf * 4 + nf) * 4 + c2];
                    #pragma unroll
                    for (int mf = 0; mf < 2; mf++)
                        #pragma unroll
                        for (int c2 = 0; c2 < 4; c2++)
                            fca[mf][c2] += sp[32 + mf * 4 + c2];
                }

                float* crow = cS + l * 64 * 8;
                float* op = out + (size_t)(t - 1) * BATCH * HID;
                #pragma unroll
                for (int mf = 0; mf < 2; mf++) {
                    #pragma unroll
                    for (int rp = 0; rp < 2; rp++) {
                        const int b = m2 * 32 + mf * 16 + r + rp * 8;
                        const int k = rp * 2;
                        #pragma unroll
                        for (int ug = 0; ug < 2; ug++) {
                            const int u = ug * 4 + a4;
                            float iv = acc[mf][ug * 2 + 0][k + 0] + biasS[l * 32 + ug * 16 + a4 * 2 + 0];
                            float fv = acc[mf][ug * 2 + 0][k + 1] + biasS[l * 32 + ug * 16 + a4 * 2 + 1];
                            float gv = acc[mf][ug * 2 + 1][k + 0] + biasS[l * 32 + ug * 16 + 8 + a4 * 2 + 0];
                            float ov = acc[mf][ug * 2 + 1][k + 1] + biasS[l * 32 + ug * 16 + 8 + a4 * 2 + 1];
                            float cn = sig_(fv) * crow[b * 8 + u] + sig_(iv) * tanhf(gv);
                            crow[b * 8 + u] = cn;
                            hdst[b * HID + j0 + u] = __float2half_rn(sig_(ov) * tanhf(cn));
                        }
                        if (fc_phase) {
                            op[b * HID + j0 + a4 * 2 + 0] = fca[mf][k + 0] + fcbS[a4 * 2 + 0];
                            op[b * HID + j0 + a4 * 2 + 1] = fca[mf][k + 1] + fcbS[a4 * 2 + 1];
                        }
                    }
                }
            }
            gbar_arrive();
            barTarget += NCTA;
            if (!last_phase) {
                // stage next phase's part-A chunk 1 (chunk 0 staged at B kc=6)
                stage_act(xbufS + s_stage * ABUFH, nhsrc, KC, tid);
                cp_commit();
                s_stage = NX3(s_stage);
            }
        }
    }

    // ===== final FC for t = T-1 (x = h1 written at t=127, parity 1) =====
    {
        gbar_wait(barTarget);
        const __half* xsrc = g_hbuf + (2 + 1) * BATCH * HID;
        const __half* wsrc = g_Wst + (size_t)(0 * NCTA + cta) * 40 * HID;
        float fca[2][4] = {{0,0,0,0},{0,0,0,0}};
        #pragma unroll
        for (int i = 0; i < 2; i++) {
            stage_act(xbufS + s_stage * ABUFH, xsrc, i * KC, tid);
            stage_w40(wbufS + w_stage * WBUFH, wsrc, i * KC, tid);
            cp_commit();
            s_stage = NX3(s_stage); w_stage = NX3(w_stage);
        }
        #pragma unroll 1
        for (int kc = 0; kc < NKC; kc++) {
            cp_wait<1>();
            __syncthreads();
            if (kc + 2 < NKC) {
                stage_act(xbufS + s_stage * ABUFH, xsrc, (kc + 2) * KC, tid);
                stage_w40(wbufS + w_stage * WBUFH, wsrc, (kc + 2) * KC, tid);
                s_stage = NX3(s_stage); w_stage = NX3(w_stage);
            }
            cp_commit();
            const unsigned xd = (unsigned)s_cons * ABUF;
            const unsigned wd = (unsigned)w_cons * WBUF;
            s_cons = NX3(s_cons); w_cons = NX3(w_cons);
            #pragma unroll
            for (int j = 0; j < 2; j++) {
                const int k16 = ks + j * 4;
                unsigned f0, f1;
                ldsm_x2(f0, f1, fcB0 + wd + k16 * 32);
                #pragma unroll
                for (int mf = 0; mf < 2; mf++) {
                    unsigned a0, a1, a2, a3;
                    ldsm_x4(a0, a1, a2, a3, xbA0[mf] + xd + k16 * 32);
                    hmma(fca[mf], a0, a1, a2, a3, f0, f1);
                }
            }
        }
        __syncthreads();
        if (ks > 0) {
            float* sp = wscr + (((ks - 1) * 2 + m2) * 32 + lane) * 40;
            #pragma unroll
            for (int mf = 0; mf < 2; mf++)
                #pragma unroll
                for (int c2 = 0; c2 < 4; c2++)
                    sp[32 + mf * 4 + c2] = fca[mf][c2];
        }
        __syncthreads();
        if (ks == 0) {
            #pragma unroll
            for (int sl = 0; sl < 3; sl++) {
                const float* sp = wscr + ((sl * 2 + m2) * 32 + lane) * 40;
                #pragma unroll
                for (int mf = 0; mf < 2; mf++)
                    #pragma unroll
                    for (int c2 = 0; c2 < 4; c2++)
                        fca[mf][c2] += sp[32 + mf * 4 + c2];
            }
            float* op = out + (size_t)(TSTEPS - 1) * BATCH * HID;
            #pragma unroll
            for (int mf = 0; mf < 2; mf++)
                #pragma unroll
                for (int rp = 0; rp < 2; rp++) {
                    const int b = m2 * 32 + mf * 16 + r + rp * 8;
                    const int k = rp * 2;
                    op[b * HID + j0 + a4 * 2 + 0] = fca[mf][k + 0] + fcbS[a4 * 2 + 0];
                    op[b * HID + j0 + a4 * 2 + 1] = fca[mf][k + 1] + fcbS[a4 * 2 + 1];
                }
        }
    }
}

// ---------------- host launch -----------------------------------------------
extern "C" void kernel_launch(void* const* d_in, const int* in_sizes, int n_in,
                              void* d_out, int out_size) {
    const float* h0  = (const float*)d_in[0];
    const float* Wih = (const float*)d_in[1];
    const float* Whh = (const float*)d_in[2];
    const float* bih = (const float*)d_in[3];
    const float* bhh = (const float*)d_in[4];
    const float* Wfc = (const float*)d_in[5];
    const float* bfc = (const float*)d_in[6];
    float* out = (float*)d_out;

    const int smem = (2 * 32 * SR + 3 * 64 * SA + 3 * 40 * SW) * 2
                   + (2 * 64 * 8 + 64 + 8) * 4;
    cudaFuncSetAttribute(lstm_persist, cudaFuncAttributeMaxDynamicSharedMemorySize, smem);

    prep_all<<<2048, 256>>>(Wih, Whh, h0, Wfc);
    lstm_persist<<<NCTA, THREADS, smem>>>(bih, bhh, bfc, out);
}